// round 2
// baseline (speedup 1.0000x reference)
#include <cuda_runtime.h>
#include <math.h>
#include <stdint.h>

#define B_  2
#define S_  2048
#define H_  16
#define DK_ 64
#define DM_ 1024
#define M_  (B_ * S_)   // 4096

// Scratch ([B,H,S,Dk] layouts), zero-init device globals (no allocs).
__device__ float g_Q[B_ * H_ * S_ * DK_];
__device__ float g_K[B_ * H_ * S_ * DK_];
__device__ float g_V[B_ * H_ * S_ * DK_];
__device__ float g_A[B_ * H_ * S_ * DK_];

__device__ __forceinline__ uint32_t f2tf(float f) {
    uint32_t u;
    asm("cvt.rna.tf32.f32 %0, %1;" : "=r"(u) : "f"(f));
    return u;
}

__device__ __forceinline__ void mma_tf32(float4& c,
                                         uint32_t a0, uint32_t a1, uint32_t a2, uint32_t a3,
                                         uint32_t b0, uint32_t b1)
{
    asm volatile(
        "mma.sync.aligned.m16n8k8.row.col.f32.tf32.tf32.f32 "
        "{%0,%1,%2,%3}, {%4,%5,%6,%7}, {%8,%9}, {%0,%1,%2,%3};"
        : "+f"(c.x), "+f"(c.y), "+f"(c.z), "+f"(c.w)
        : "r"(a0), "r"(a1), "r"(a2), "r"(a3), "r"(b0), "r"(b1));
}

// ---------------------------------------------------------------------------
// TF32 tensor-core GEMM: C[M,1024] = A[M,1024] @ Bw[1024,1024] + bias
// CTA tile 128x128, BK=16, 256 threads = 8 warps (2m x 4n), warp tile 64x32.
// MODE 0: A row-major x; C scattered to [B,H,S,Dk] (QKV projections).
// MODE 1: A gathered from [B,H,S,Dk]; C row-major (output projection).
// ---------------------------------------------------------------------------
template <int MODE>
__global__ __launch_bounds__(256, 1)
void gemm_tc(const float* __restrict__ A,
             const float* __restrict__ Bw,
             const float* __restrict__ bias,
             float* __restrict__ C)
{
    __shared__ uint32_t As[128][20];   // [m][k], pad 20 -> conflict-free frag loads
    __shared__ uint32_t Bs[16][132];   // [k][n], pad 132

    const int tid = threadIdx.x;
    const int m0 = blockIdx.y * 128;
    const int n0 = blockIdx.x * 128;
    const int w    = tid >> 5;
    const int lane = tid & 31;
    const int wm = (w >> 2) * 64;   // warp m offset (0 or 64)
    const int wn = (w & 3) * 32;    // warp n offset (0,32,64,96)
    const int g = lane >> 2;        // 0..7
    const int t = lane & 3;         // 0..3

    float4 pa[2], pb[2];

    float4 acc[4][4];
#pragma unroll
    for (int i = 0; i < 4; i++)
#pragma unroll
        for (int j = 0; j < 4; j++) acc[i][j] = make_float4(0.f, 0.f, 0.f, 0.f);

    // --- tile loaders ---
    auto ldg_tile = [&](int k0) {
#pragma unroll
        for (int r = 0; r < 2; r++) {
            int idx = r * 1024 + tid * 4;
            int m = idx >> 4, kc = idx & 15;
            if (MODE == 0) {
                pa[r] = *(const float4*)&A[(size_t)(m0 + m) * DM_ + k0 + kc];
            } else {
                int mm = m0 + m;
                int b = mm >> 11, s = mm & (S_ - 1);
                int k = k0 + kc;
                int h = k >> 6, d = k & 63;
                pa[r] = *(const float4*)&A[(((size_t)(b * H_ + h) * S_ + s) * DK_) + d];
            }
            int kb = idx >> 7, n = idx & 127;
            pb[r] = *(const float4*)&Bw[(size_t)(k0 + kb) * DM_ + n0 + n];
        }
    };
    auto sts_tile = [&]() {
#pragma unroll
        for (int r = 0; r < 2; r++) {
            int idx = r * 1024 + tid * 4;
            int m = idx >> 4, kc = idx & 15;
            As[m][kc + 0] = f2tf(pa[r].x);
            As[m][kc + 1] = f2tf(pa[r].y);
            As[m][kc + 2] = f2tf(pa[r].z);
            As[m][kc + 3] = f2tf(pa[r].w);
            int kb = idx >> 7, n = idx & 127;
            Bs[kb][n + 0] = f2tf(pb[r].x);
            Bs[kb][n + 1] = f2tf(pb[r].y);
            Bs[kb][n + 2] = f2tf(pb[r].z);
            Bs[kb][n + 3] = f2tf(pb[r].w);
        }
    };

    ldg_tile(0);
    sts_tile();
    __syncthreads();

    const int NIT = DM_ / 16;   // 64
    for (int it = 0; it < NIT; ++it) {
        if (it + 1 < NIT) ldg_tile((it + 1) * 16);

#pragma unroll
        for (int ks = 0; ks < 2; ks++) {
            const int k8 = ks * 8;
            uint32_t af[4][4], bf[4][2];
#pragma unroll
            for (int i = 0; i < 4; i++) {
                int mr = wm + i * 16 + g;
                af[i][0] = As[mr][k8 + t];
                af[i][1] = As[mr + 8][k8 + t];
                af[i][2] = As[mr][k8 + t + 4];
                af[i][3] = As[mr + 8][k8 + t + 4];
            }
#pragma unroll
            for (int j = 0; j < 4; j++) {
                int nc = wn + j * 8 + g;
                bf[j][0] = Bs[k8 + t][nc];
                bf[j][1] = Bs[k8 + t + 4][nc];
            }
#pragma unroll
            for (int i = 0; i < 4; i++)
#pragma unroll
                for (int j = 0; j < 4; j++)
                    mma_tf32(acc[i][j], af[i][0], af[i][1], af[i][2], af[i][3],
                             bf[j][0], bf[j][1]);
        }
        __syncthreads();
        if (it + 1 < NIT) {
            sts_tile();
            __syncthreads();
        }
    }

    // Epilogue: c0:(g,2t) c1:(g,2t+1) c2:(g+8,2t) c3:(g+8,2t+1)
#pragma unroll
    for (int i = 0; i < 4; i++) {
        int r0 = m0 + wm + i * 16 + g;
        int r1 = r0 + 8;
#pragma unroll
        for (int j = 0; j < 4; j++) {
            int c0 = n0 + wn + j * 8 + 2 * t;
            float bx = bias[c0], by = bias[c0 + 1];
            float2 v0 = make_float2(acc[i][j].x + bx, acc[i][j].y + by);
            float2 v1 = make_float2(acc[i][j].z + bx, acc[i][j].w + by);
            if (MODE == 0) {
                int h = c0 >> 6, d = c0 & 63;
                int b0i = r0 >> 11, s0i = r0 & (S_ - 1);
                int b1i = r1 >> 11, s1i = r1 & (S_ - 1);
                *(float2*)&C[(((size_t)(b0i * H_ + h) * S_ + s0i) * DK_) + d] = v0;
                *(float2*)&C[(((size_t)(b1i * H_ + h) * S_ + s1i) * DK_) + d] = v1;
            } else {
                *(float2*)&C[(size_t)r0 * DM_ + c0] = v0;
                *(float2*)&C[(size_t)r1 * DM_ + c0] = v1;
            }
        }
    }
}

// ---------------------------------------------------------------------------
// Flash-attention v2: 256 threads, 128 queries/CTA, 2 threads per query
// (each owns 32 of the 64 head dims). Scores kept in registers (no smem pass).
// ---------------------------------------------------------------------------
__global__ __launch_bounds__(256, 1)
void flash_attn()
{
    __shared__ float Ks[32 * 64];   // 8 KB
    __shared__ float Vs[32 * 64];   // 8 KB

    const int tid = threadIdx.x;
    const int q   = tid >> 1;       // 0..127
    const int h   = tid & 1;        // half of head dim
    const int bh  = blockIdx.y;
    const int row = blockIdx.x * 128 + q;

    const float scale = 0.125f;   // 1/sqrt(64)

    const float* Qp = g_Q + ((size_t)bh * S_ + row) * DK_ + h * 32;
    float4 qf[8];
#pragma unroll
    for (int i = 0; i < 8; i++) {
        float4 v = *(const float4*)&Qp[i * 4];
        qf[i] = make_float4(v.x * scale, v.y * scale, v.z * scale, v.w * scale);
    }

    float4 acc[8];
#pragma unroll
    for (int i = 0; i < 8; i++) acc[i] = make_float4(0.f, 0.f, 0.f, 0.f);

    float s[32];
    float mrun = -1e30f;
    float l = 0.f;

    for (int kt = 0; kt < S_ / 32; kt++) {
        const float* Kg = g_K + ((size_t)bh * S_ + kt * 32) * DK_;
        const float* Vg = g_V + ((size_t)bh * S_ + kt * 32) * DK_;
#pragma unroll
        for (int r = 0; r < 2; r++) {
            int lin = r * 1024 + tid * 4;
            *(float4*)&Ks[lin] = *(const float4*)&Kg[lin];
            *(float4*)&Vs[lin] = *(const float4*)&Vg[lin];
        }
        __syncthreads();

        // Pass 1: 32-dim partial dots, pair-combine via shfl, tile max
        float tm = -1e30f;
#pragma unroll
        for (int j = 0; j < 32; j++) {
            const float4* kr = (const float4*)&Ks[j * 64 + h * 32];
            float p0 = 0.f, p1 = 0.f;
#pragma unroll
            for (int i = 0; i < 8; i += 2) {
                float4 k0 = kr[i], k1 = kr[i + 1];
                p0 += qf[i].x * k0.x + qf[i].y * k0.y + qf[i].z * k0.z + qf[i].w * k0.w;
                p1 += qf[i + 1].x * k1.x + qf[i + 1].y * k1.y + qf[i + 1].z * k1.z + qf[i + 1].w * k1.w;
            }
            float part = p0 + p1;
            part += __shfl_xor_sync(0xffffffffu, part, 1);
            s[j] = part;
            tm = fmaxf(tm, part);
        }

        // Online softmax rescale
        float mnew = fmaxf(mrun, tm);
        float corr = __expf(mrun - mnew);
        l *= corr;
#pragma unroll
        for (int i = 0; i < 8; i++) {
            acc[i].x *= corr; acc[i].y *= corr; acc[i].z *= corr; acc[i].w *= corr;
        }

        // Pass 2: P @ V (each thread its 32-dim half)
#pragma unroll
        for (int j = 0; j < 32; j++) {
            float p = __expf(s[j] - mnew);
            l += p;
            const float4* vr = (const float4*)&Vs[j * 64 + h * 32];
#pragma unroll
            for (int i = 0; i < 8; i++) {
                float4 v = vr[i];
                acc[i].x = fmaf(p, v.x, acc[i].x);
                acc[i].y = fmaf(p, v.y, acc[i].y);
                acc[i].z = fmaf(p, v.z, acc[i].z);
                acc[i].w = fmaf(p, v.w, acc[i].w);
            }
        }
        mrun = mnew;
        __syncthreads();
    }

    float inv = 1.f / l;
    float* Op = g_A + ((size_t)bh * S_ + row) * DK_ + h * 32;
#pragma unroll
    for (int i = 0; i < 8; i++) {
        float4 o = make_float4(acc[i].x * inv, acc[i].y * inv,
                               acc[i].z * inv, acc[i].w * inv);
        *(float4*)&Op[i * 4] = o;
    }
}

// ---------------------------------------------------------------------------
// Launch
// ---------------------------------------------------------------------------
extern "C" void kernel_launch(void* const* d_in, const int* in_sizes, int n_in,
                              void* d_out, int out_size)
{
    const float* x   = (const float*)d_in[0];
    const float* w_q = (const float*)d_in[1];
    const float* b_q = (const float*)d_in[2];
    const float* w_k = (const float*)d_in[3];
    const float* b_k = (const float*)d_in[4];
    const float* w_v = (const float*)d_in[5];
    const float* b_v = (const float*)d_in[6];
    const float* w_o = (const float*)d_in[7];
    const float* b_o = (const float*)d_in[8];
    float* out = (float*)d_out;

    float *pQ, *pK, *pV, *pA;
    cudaGetSymbolAddress((void**)&pQ, g_Q);
    cudaGetSymbolAddress((void**)&pK, g_K);
    cudaGetSymbolAddress((void**)&pV, g_V);
    cudaGetSymbolAddress((void**)&pA, g_A);

    dim3 ggrid(DM_ / 128, M_ / 128);   // (8, 32)
    dim3 gblk(256);

    gemm_tc<0><<<ggrid, gblk>>>(x, w_q, b_q, pQ);
    gemm_tc<0><<<ggrid, gblk>>>(x, w_k, b_k, pK);
    gemm_tc<0><<<ggrid, gblk>>>(x, w_v, b_v, pV);

    dim3 agrid(S_ / 128, B_ * H_);     // (16, 32)
    flash_attn<<<agrid, 256>>>();

    gemm_tc<1><<<ggrid, gblk>>>(pA, w_o, b_o, out);
}